// round 1
// baseline (speedup 1.0000x reference)
#include <cuda_runtime.h>
#include <math.h>

#define HW 65536            // 256*256
#define BATCH 2
#define NPIX (BATCH*HW)     // 131072
#define NW 1024             // windows per batch (32x32)
#define KEEP 512

// ---------------- scratch (device globals; no allocation) ----------------
__device__ float g_q[NPIX*64];     // NHWC
__device__ float g_k[NPIX*64];     // NHWC
__device__ float g_v[NPIX*64];     // NHWC
__device__ float g_mix[NPIX*64];   // NHWC (attention output for hard windows)
__device__ float g_h1[NPIX*17];    // per-pixel 17 channels contiguous
__device__ float g_sa[NPIX];
__device__ float g_xm[NPIX];
__device__ float g_score[BATCH*NW];
__device__ int   g_hard[BATCH*KEEP];
__device__ int   g_ishard[BATCH*NW];

// ---------------- K1: qkv 1x1 convs (NCHW in -> NHWC out) ----------------
__global__ __launch_bounds__(128) void k_qkv(
    const float* __restrict__ x,
    const float* __restrict__ Wq, const float* __restrict__ bq,
    const float* __restrict__ Wk, const float* __restrict__ bk,
    const float* __restrict__ Wv, const float* __restrict__ bv)
{
    __shared__ float sW[3*4096];
    for (int i = threadIdx.x; i < 4096; i += 128) {
        sW[i]        = Wq[i];
        sW[4096 + i] = Wk[i];
        sW[8192 + i] = Wv[i];
    }
    __syncthreads();
    int g = blockIdx.x * 128 + threadIdx.x;      // 0..131071
    int b = g >> 16, p = g & (HW - 1);
    const float* xb = x + (size_t)b * 64 * HW + p;
    float xr[64];
#pragma unroll
    for (int ic = 0; ic < 64; ic++) xr[ic] = xb[(size_t)ic * HW];

    float* oq = g_q + (size_t)g * 64;
    float* ok = g_k + (size_t)g * 64;
    float* ov = g_v + (size_t)g * 64;
    for (int oc = 0; oc < 64; oc++) {
        float aq = bq[oc], ak = bk[oc], av = bv[oc];
        const float* wq = &sW[oc * 64];
        const float* wk = &sW[4096 + oc * 64];
        const float* wv = &sW[8192 + oc * 64];
#pragma unroll
        for (int ic = 0; ic < 64; ic++) {
            aq += xr[ic] * wq[ic];
            ak += xr[ic] * wk[ic];
            av += xr[ic] * wv[ic];
        }
        oq[oc] = aq; ok[oc] = ak; ov[oc] = av;
    }
}

// ---------------- K2: pin conv + LayerNorm + lrelu + xm ----------------
__global__ __launch_bounds__(256) void k_pin(
    const float* __restrict__ cg,
    const float* __restrict__ pinW, const float* __restrict__ pinb,
    const float* __restrict__ lnw,  const float* __restrict__ lnb)
{
    __shared__ float sw[17*68];
    __shared__ float sb[17], slw[17], slb[17];
    for (int i = threadIdx.x; i < 17*68; i += 256) sw[i] = pinW[i];
    if (threadIdx.x < 17) {
        sb[threadIdx.x]  = pinb[threadIdx.x];
        slw[threadIdx.x] = lnw[threadIdx.x];
        slb[threadIdx.x] = lnb[threadIdx.x];
    }
    __syncthreads();
    int g = blockIdx.x * 256 + threadIdx.x;
    int b = g >> 16, p = g & (HW - 1);
    int y = p >> 8, xx = p & 255;

    float cond[68];
    const float4* vp4 = (const float4*)(g_v + (size_t)g * 64);
#pragma unroll
    for (int i = 0; i < 16; i++) {
        float4 t = vp4[i];
        cond[4*i+0] = t.x; cond[4*i+1] = t.y; cond[4*i+2] = t.z; cond[4*i+3] = t.w;
    }
    cond[64] = cg[(size_t)b * 2 * HW + p];
    cond[65] = cg[(size_t)b * 2 * HW + HW + p];
    cond[66] = -1.0f + (2.0f / 7.0f) * (float)(y & 7);
    cond[67] = -1.0f + (2.0f / 7.0f) * (float)(xx & 7);

    float h[17];
    for (int oc = 0; oc < 17; oc++) {
        float a = sb[oc];
        const float* w = &sw[oc * 68];
#pragma unroll
        for (int ic = 0; ic < 68; ic++) a += cond[ic] * w[ic];
        h[oc] = a;
    }
    float u = 0.f;
#pragma unroll
    for (int oc = 0; oc < 17; oc++) u += h[oc];
    u *= (1.0f / 17.0f);
    float sv = 0.f;
#pragma unroll
    for (int oc = 0; oc < 17; oc++) { float d = h[oc] - u; sv += d * d; }
    sv *= (1.0f / 17.0f);
    float inv = rsqrtf(sv + 1e-6f);

    float xs = 0.f;
    float* hp = g_h1 + (size_t)g * 17;
#pragma unroll
    for (int oc = 0; oc < 17; oc++) {
        float tv = slw[oc] * (h[oc] - u) * inv + slb[oc];
        tv = (tv >= 0.f) ? tv : 0.1f * tv;
        hp[oc] = tv;
        xs += tv;
    }
    g_xm[g] = xs * (1.0f / 17.0f);
}

// ---------------- K3: 3x3 conv (17->1) + sigmoid ----------------
__global__ __launch_bounds__(256) void k_sa(
    const float* __restrict__ saW, const float* __restrict__ sab)
{
    __shared__ float swt[153];
    for (int i = threadIdx.x; i < 153; i += 256) swt[i] = saW[i];
    __syncthreads();
    int g = blockIdx.x * 256 + threadIdx.x;
    int b = g >> 16, p = g & (HW - 1);
    int y = p >> 8, x = p & 255;
    float acc = sab[0];
#pragma unroll
    for (int dy = -1; dy <= 1; dy++) {
        int yy = y + dy;
        if (yy < 0 || yy > 255) continue;
#pragma unroll
        for (int dx = -1; dx <= 1; dx++) {
            int xx = x + dx;
            if (xx < 0 || xx > 255) continue;
            const float* hp = g_h1 + ((size_t)(b * HW + yy * 256 + xx)) * 17;
            int widx = (dy + 1) * 3 + (dx + 1);
#pragma unroll
            for (int c = 0; c < 17; c++) acc += hp[c] * swt[c * 9 + widx];
        }
    }
    g_sa[g] = 1.0f / (1.0f + expf(-acc));
}

// ---------------- K4: window score MLP + softmax ----------------
__global__ __launch_bounds__(256) void k_score(
    const float* __restrict__ m1W, const float* __restrict__ m1b,
    const float* __restrict__ m2W, const float* __restrict__ m2b)
{
    int g = blockIdx.x * 256 + threadIdx.x;
    if (g >= BATCH * NW) return;
    int b = g >> 10, w = g & (NW - 1);
    int wy = w >> 5, wx = w & 31;
    float xv[64];
#pragma unroll
    for (int t = 0; t < 64; t++) {
        int qy = t >> 3, qx = t & 7;
        xv[t] = g_xm[b * HW + (wy * 8 + qy) * 256 + (wx * 8 + qx)];
    }
    float z[8];
#pragma unroll
    for (int j = 0; j < 8; j++) {
        float a = m1b[j];
        const float* w1 = m1W + j * 64;
#pragma unroll
        for (int t = 0; t < 64; t++) a += xv[t] * w1[t];
        z[j] = (a >= 0.f) ? a : 0.1f * a;
    }
    float l0 = m2b[0], l1 = m2b[1];
#pragma unroll
    for (int j = 0; j < 8; j++) { l0 += z[j] * m2W[j]; l1 += z[j] * m2W[8 + j]; }
    float mm = fmaxf(l0, l1);
    float e0 = expf(l0 - mm), e1 = expf(l1 - mm);
    g_score[g] = e0 / (e0 + e1);
}

// ---------------- K5: deterministic rank -> top-512 selection ----------------
__global__ __launch_bounds__(1024) void k_rank()
{
    __shared__ float s[NW];
    int b = blockIdx.x;
    int i = threadIdx.x;
    s[i] = g_score[b * NW + i];
    __syncthreads();
    float si = s[i];
    int r = 0;
    for (int j = 0; j < NW; j++) {
        float sj = s[j];
        r += (sj > si) || (sj == si && j < i);   // stable argsort(-score) tie-break
    }
    if (r < KEEP) {
        g_hard[b * KEEP + r] = i;
        g_ishard[b * NW + i] = 1;
    } else {
        g_ishard[b * NW + i] = 0;
    }
}

// ---------------- K6: windowed attention with 2D relative position bias ----------------
__device__ __forceinline__ float dot16(const float4* kr, const float* q)
{
    float4 a = kr[0], b = kr[1], c = kr[2], d = kr[3];
    return q[0]*a.x + q[1]*a.y + q[2]*a.z + q[3]*a.w
         + q[4]*b.x + q[5]*b.y + q[6]*b.z + q[7]*b.w
         + q[8]*c.x + q[9]*c.y + q[10]*c.z + q[11]*c.w
         + q[12]*d.x + q[13]*d.y + q[14]*d.z + q[15]*d.w;
}

__global__ __launch_bounds__(64) void k_attn(
    const float* __restrict__ relh, const float* __restrict__ relw)
{
    __shared__ __align__(16) float ksh[144*16];
    __shared__ __align__(16) float vsh[144*16];
    __shared__ float srw[23*16];
    __shared__ float srh[23*16];

    int t = threadIdx.x;                 // q token 0..63
    int b = blockIdx.x >> 9;             // 512 windows per batch
    int w = g_hard[blockIdx.x];
    int h = blockIdx.y;                  // head
    int wy = w >> 5, wx = w & 31;

    for (int i = t; i < 23*16; i += 64) { srw[i] = relw[i]; srh[i] = relh[i]; }

    int y0 = wy * 8 - 2, x0 = wx * 8 - 2;
    for (int kk = t; kk < 144; kk += 64) {
        int ky = kk / 12, kx = kk - ky * 12;
        int yy = y0 + ky, xx = x0 + kx;
        float4* kd = (float4*)&ksh[kk * 16];
        float4* vd = (float4*)&vsh[kk * 16];
        if (yy >= 0 && yy < 256 && xx >= 0 && xx < 256) {
            size_t base = ((size_t)(b * HW + yy * 256 + xx)) * 64 + h * 16;
            const float4* kp = (const float4*)(g_k + base);
            const float4* vp = (const float4*)(g_v + base);
#pragma unroll
            for (int i = 0; i < 4; i++) { kd[i] = kp[i]; vd[i] = vp[i]; }
        } else {
            float4 z = make_float4(0.f, 0.f, 0.f, 0.f);
#pragma unroll
            for (int i = 0; i < 4; i++) { kd[i] = z; vd[i] = z; }
        }
    }
    __syncthreads();

    int qy = t >> 3, qx = t & 7;
    int py = wy * 8 + qy, px = wx * 8 + qx;
    size_t qbase = ((size_t)(b * HW + py * 256 + px)) * 64 + h * 16;

    float q[16];
    const float scale = 0.25f;           // DH^-0.5, DH=16
    const float4* qp = (const float4*)(g_q + qbase);
#pragma unroll
    for (int i = 0; i < 4; i++) {
        float4 v = qp[i];
        q[4*i+0] = v.x * scale; q[4*i+1] = v.y * scale;
        q[4*i+2] = v.z * scale; q[4*i+3] = v.w * scale;
    }

    // relative bias per key column / row
    float rwv[12], rhv[12];
#pragma unroll
    for (int k2 = 0; k2 < 12; k2++) {
        const float* pw = &srw[(k2 - qx + 11) * 16];
        const float* ph = &srh[(k2 - qy + 11) * 16];
        float a = 0.f, c = 0.f;
#pragma unroll
        for (int d = 0; d < 16; d++) { a += q[d] * pw[d]; c += q[d] * ph[d]; }
        rwv[k2] = a; rhv[k2] = c;
    }

    // pass 1: online max + sum
    float m = -1e30f, ssum = 0.f;
    for (int ky = 0; ky < 12; ky++) {
        float rh2 = rhv[ky];
#pragma unroll
        for (int kx = 0; kx < 12; kx++) {
            int kk = ky * 12 + kx;
            float l = dot16((const float4*)&ksh[kk * 16], q) + rwv[kx] + rh2;
            float mn = fmaxf(m, l);
            ssum = ssum * expf(m - mn) + expf(l - mn);
            m = mn;
        }
    }
    float inv = 1.0f / ssum;

    // pass 2: recompute logits, accumulate weighted V
    float4 a0 = make_float4(0,0,0,0), a1 = a0, a2 = a0, a3 = a0;
    for (int ky = 0; ky < 12; ky++) {
        float rh2 = rhv[ky];
#pragma unroll
        for (int kx = 0; kx < 12; kx++) {
            int kk = ky * 12 + kx;
            float l = dot16((const float4*)&ksh[kk * 16], q) + rwv[kx] + rh2;
            float wgt = expf(l - m) * inv;
            const float4* vr = (const float4*)&vsh[kk * 16];
            float4 v0 = vr[0], v1 = vr[1], v2 = vr[2], v3 = vr[3];
            a0.x += wgt * v0.x; a0.y += wgt * v0.y; a0.z += wgt * v0.z; a0.w += wgt * v0.w;
            a1.x += wgt * v1.x; a1.y += wgt * v1.y; a1.z += wgt * v1.z; a1.w += wgt * v1.w;
            a2.x += wgt * v2.x; a2.y += wgt * v2.y; a2.z += wgt * v2.z; a2.w += wgt * v2.w;
            a3.x += wgt * v3.x; a3.y += wgt * v3.y; a3.z += wgt * v3.z; a3.w += wgt * v3.w;
        }
    }
    float4* op = (float4*)(g_mix + qbase);
    op[0] = a0; op[1] = a1; op[2] = a2; op[3] = a3;
}

// ---------------- K7: final 1x1 conv, fusing easy-path (v*sa) selection ----------------
__global__ __launch_bounds__(128) void k_final(
    const float* __restrict__ Wout, const float* __restrict__ bout,
    float* __restrict__ out)
{
    __shared__ float sw[4096];
    __shared__ float sb[64];
    for (int i = threadIdx.x; i < 4096; i += 128) sw[i] = Wout[i];
    if (threadIdx.x < 64) sb[threadIdx.x] = bout[threadIdx.x];
    __syncthreads();

    int g = blockIdx.x * 128 + threadIdx.x;
    int b = g >> 16, p = g & (HW - 1);
    int y = p >> 8, x = p & 255;
    int w = (y >> 3) * 32 + (x >> 3);

    float mv[64];
    if (g_ishard[b * NW + w]) {
        const float4* mp = (const float4*)(g_mix + (size_t)g * 64);
#pragma unroll
        for (int i = 0; i < 16; i++) {
            float4 t4 = mp[i];
            mv[4*i+0] = t4.x; mv[4*i+1] = t4.y; mv[4*i+2] = t4.z; mv[4*i+3] = t4.w;
        }
    } else {
        float s = g_sa[g];
        const float4* vp = (const float4*)(g_v + (size_t)g * 64);
#pragma unroll
        for (int i = 0; i < 16; i++) {
            float4 t4 = vp[i];
            mv[4*i+0] = t4.x * s; mv[4*i+1] = t4.y * s;
            mv[4*i+2] = t4.z * s; mv[4*i+3] = t4.w * s;
        }
    }

    float* ob = out + (size_t)b * 64 * HW + p;
    for (int oc = 0; oc < 64; oc++) {
        float a = sb[oc];
        const float* wr = &sw[oc * 64];
#pragma unroll
        for (int ic = 0; ic < 64; ic++) a += mv[ic] * wr[ic];
        ob[(size_t)oc * HW] = a;
    }
}

// ---------------- launch ----------------
extern "C" void kernel_launch(void* const* d_in, const int* in_sizes, int n_in,
                              void* d_out, int out_size)
{
    const float* x    = (const float*)d_in[0];
    const float* cg   = (const float*)d_in[1];
    const float* Wq   = (const float*)d_in[2];
    const float* bq   = (const float*)d_in[3];
    const float* Wk   = (const float*)d_in[4];
    const float* bk   = (const float*)d_in[5];
    const float* Wv   = (const float*)d_in[6];
    const float* bv   = (const float*)d_in[7];
    const float* Wout = (const float*)d_in[8];
    const float* bout = (const float*)d_in[9];
    const float* relh = (const float*)d_in[10];
    const float* relw = (const float*)d_in[11];
    const float* pinW = (const float*)d_in[12];
    const float* pinb = (const float*)d_in[13];
    const float* lnw  = (const float*)d_in[14];
    const float* lnb  = (const float*)d_in[15];
    const float* saW  = (const float*)d_in[16];
    const float* sab  = (const float*)d_in[17];
    const float* m1W  = (const float*)d_in[18];
    const float* m1b  = (const float*)d_in[19];
    const float* m2W  = (const float*)d_in[20];
    const float* m2b  = (const float*)d_in[21];
    float* out = (float*)d_out;

    k_qkv  <<<NPIX / 128, 128>>>(x, Wq, bq, Wk, bk, Wv, bv);
    k_pin  <<<NPIX / 256, 256>>>(cg, pinW, pinb, lnw, lnb);
    k_sa   <<<NPIX / 256, 256>>>(saW, sab);
    k_score<<<(BATCH * NW) / 256, 256>>>(m1W, m1b, m2W, m2b);
    k_rank <<<BATCH, 1024>>>();
    k_attn <<<dim3(BATCH * KEEP, 4), 64>>>(relh, relw);
    k_final<<<NPIX / 128, 128>>>(Wout, bout, out);
}

// round 2
// speedup vs baseline: 1.0635x; 1.0635x over previous
#include <cuda_runtime.h>
#include <math.h>

#define HW 65536            // 256*256
#define BATCH 2
#define NPIX (BATCH*HW)     // 131072
#define NW 1024             // windows per batch (32x32)
#define KEEP 512

typedef unsigned long long u64;

// ---------------- packed f32x2 helpers (Blackwell) ----------------
__device__ __forceinline__ u64 fma2(u64 a, u64 b, u64 c) {
    u64 d; asm("fma.rn.f32x2 %0,%1,%2,%3;" : "=l"(d) : "l"(a), "l"(b), "l"(c)); return d;
}
__device__ __forceinline__ u64 mul2(u64 a, u64 b) {
    u64 d; asm("mul.rn.f32x2 %0,%1,%2;" : "=l"(d) : "l"(a), "l"(b)); return d;
}
__device__ __forceinline__ u64 pack2(float lo, float hi) {
    u64 r; asm("mov.b64 %0,{%1,%2};" : "=l"(r) : "f"(lo), "f"(hi)); return r;
}
__device__ __forceinline__ float hadd2(u64 v) {
    float lo, hi; asm("mov.b64 {%0,%1},%2;" : "=f"(lo), "=f"(hi) : "l"(v)); return lo + hi;
}

// ---------------- scratch (device globals; no allocation) ----------------
__device__ float g_q[NPIX*64];     // NHWC
__device__ float g_k[NPIX*64];     // NHWC
__device__ float g_v[NPIX*64];     // NHWC
__device__ float g_mix[NPIX*64];   // NHWC (attention output for hard windows)
__device__ float g_h1[NPIX*18];    // per-pixel 17 channels (stride 18 for 8B alignment)
__device__ float g_sa[NPIX];
__device__ float g_xm[NPIX];
__device__ float g_score[BATCH*NW];
__device__ int   g_hard[BATCH*KEEP];
__device__ int   g_ishard[BATCH*NW];

// ---------------- K1: qkv 1x1 convs (NCHW in -> NHWC out), FFMA2 ----------------
__global__ __launch_bounds__(128) void k_qkv(
    const float* __restrict__ x,
    const float* __restrict__ Wq, const float* __restrict__ bq,
    const float* __restrict__ Wk, const float* __restrict__ bk,
    const float* __restrict__ Wv, const float* __restrict__ bv)
{
    __shared__ u64 sW[3*2048];   // 48 KB: q,k,v weights as ic-pairs (natural layout)
    const u64* wq64 = (const u64*)Wq;
    const u64* wk64 = (const u64*)Wk;
    const u64* wv64 = (const u64*)Wv;
    for (int i = threadIdx.x; i < 2048; i += 128) {
        sW[i]        = wq64[i];
        sW[2048 + i] = wk64[i];
        sW[4096 + i] = wv64[i];
    }
    __syncthreads();

    int g = blockIdx.x * 128 + threadIdx.x;
    int b = g >> 16, p = g & (HW - 1);
    const float* xb = x + (size_t)b * 64 * HW + p;
    u64 x2[32];
#pragma unroll
    for (int i = 0; i < 32; i++)
        x2[i] = pack2(xb[(size_t)(2*i) * HW], xb[(size_t)(2*i+1) * HW]);

    float* outs[3];
    outs[0] = g_q + (size_t)g * 64;
    outs[1] = g_k + (size_t)g * 64;
    outs[2] = g_v + (size_t)g * 64;
    const float* biases[3] = { bq, bk, bv };

    for (int m = 0; m < 3; m++) {
        const u64* W = &sW[m * 2048];
        u64* o64 = (u64*)outs[m];
        const float* bs = biases[m];
        for (int oc = 0; oc < 64; oc += 2) {
            const u64* w0 = &W[oc * 32];
            const u64* w1 = &W[(oc + 1) * 32];
            u64 a0 = 0, a1 = 0, c0 = 0, c1 = 0;
#pragma unroll
            for (int i = 0; i < 32; i += 2) {
                a0 = fma2(x2[i],   w0[i],   a0);
                a1 = fma2(x2[i+1], w0[i+1], a1);
                c0 = fma2(x2[i],   w1[i],   c0);
                c1 = fma2(x2[i+1], w1[i+1], c1);
            }
            float r0 = __ldg(&bs[oc])   + hadd2(a0) + hadd2(a1);
            float r1 = __ldg(&bs[oc+1]) + hadd2(c0) + hadd2(c1);
            o64[oc >> 1] = pack2(r0, r1);
        }
    }
}

// ---------------- K2: pin conv + LayerNorm + lrelu + xm, FFMA2 ----------------
__global__ __launch_bounds__(256) void k_pin(
    const float* __restrict__ cg,
    const float* __restrict__ pinW, const float* __restrict__ pinb,
    const float* __restrict__ lnw,  const float* __restrict__ lnb)
{
    __shared__ u64 sw2[17*34];     // [oc][icpair], natural (68 even)
    __shared__ float sb[17], slw[17], slb[17];
    const u64* pw64 = (const u64*)pinW;
    for (int i = threadIdx.x; i < 17*34; i += 256) sw2[i] = pw64[i];
    if (threadIdx.x < 17) {
        sb[threadIdx.x]  = pinb[threadIdx.x];
        slw[threadIdx.x] = lnw[threadIdx.x];
        slb[threadIdx.x] = lnb[threadIdx.x];
    }
    __syncthreads();

    int g = blockIdx.x * 256 + threadIdx.x;
    int b = g >> 16, p = g & (HW - 1);
    int y = p >> 8, xx = p & 255;

    u64 c2[34];
    const u64* vp = (const u64*)(g_v + (size_t)g * 64);
#pragma unroll
    for (int i = 0; i < 32; i++) c2[i] = vp[i];
    c2[32] = pack2(cg[(size_t)b * 2 * HW + p], cg[(size_t)b * 2 * HW + HW + p]);
    c2[33] = pack2(-1.0f + (2.0f / 7.0f) * (float)(y & 7),
                   -1.0f + (2.0f / 7.0f) * (float)(xx & 7));

    float h[17];
    for (int oc = 0; oc < 17; oc++) {
        const u64* w = &sw2[oc * 34];
        u64 a0 = 0, a1 = 0;
#pragma unroll
        for (int i = 0; i < 34; i += 2) {
            a0 = fma2(c2[i],   w[i],   a0);
            a1 = fma2(c2[i+1], w[i+1], a1);
        }
        h[oc] = sb[oc] + hadd2(a0) + hadd2(a1);
    }

    float u = 0.f;
#pragma unroll
    for (int oc = 0; oc < 17; oc++) u += h[oc];
    u *= (1.0f / 17.0f);
    float sv = 0.f;
#pragma unroll
    for (int oc = 0; oc < 17; oc++) { float d = h[oc] - u; sv += d * d; }
    sv *= (1.0f / 17.0f);
    float inv = rsqrtf(sv + 1e-6f);

    float xs = 0.f;
    float* hp = g_h1 + (size_t)g * 18;
#pragma unroll
    for (int oc = 0; oc < 17; oc++) {
        float tv = slw[oc] * (h[oc] - u) * inv + slb[oc];
        tv = (tv >= 0.f) ? tv : 0.1f * tv;
        hp[oc] = tv;
        xs += tv;
    }
    g_xm[g] = xs * (1.0f / 17.0f);
}

// ---------------- K3: 3x3 conv (17->1) + sigmoid, FFMA2 ----------------
__global__ __launch_bounds__(256) void k_sa(
    const float* __restrict__ saW, const float* __restrict__ sab)
{
    __shared__ u64 sw2[9*8];       // [widx][cpair] transposed for pair-contiguous c
    __shared__ float sw16[9];
    for (int i = threadIdx.x; i < 72; i += 256) {
        int widx = i >> 3, cp = i & 7;
        sw2[i] = pack2(saW[(2*cp) * 9 + widx], saW[(2*cp + 1) * 9 + widx]);
    }
    if (threadIdx.x < 9) sw16[threadIdx.x] = saW[16 * 9 + threadIdx.x];
    __syncthreads();

    int g = blockIdx.x * 256 + threadIdx.x;
    int b = g >> 16, p = g & (HW - 1);
    int y = p >> 8, x = p & 255;
    float acc = sab[0];
#pragma unroll
    for (int dy = -1; dy <= 1; dy++) {
        int yy = y + dy;
        if (yy < 0 || yy > 255) continue;
#pragma unroll
        for (int dx = -1; dx <= 1; dx++) {
            int xx = x + dx;
            if (xx < 0 || xx > 255) continue;
            const float* hp = g_h1 + ((size_t)(b * HW + yy * 256 + xx)) * 18;
            const u64* hp2 = (const u64*)hp;
            int widx = (dy + 1) * 3 + (dx + 1);
            const u64* w = &sw2[widx * 8];
            u64 a0 = 0, a1 = 0;
#pragma unroll
            for (int cp = 0; cp < 8; cp += 2) {
                a0 = fma2(hp2[cp],   w[cp],   a0);
                a1 = fma2(hp2[cp+1], w[cp+1], a1);
            }
            acc += hadd2(a0) + hadd2(a1) + hp[16] * sw16[widx];
        }
    }
    g_sa[g] = 1.0f / (1.0f + __expf(-acc));
}

// ---------------- K4: window score MLP + softmax ----------------
__global__ __launch_bounds__(256) void k_score(
    const float* __restrict__ m1W, const float* __restrict__ m1b,
    const float* __restrict__ m2W, const float* __restrict__ m2b)
{
    int g = blockIdx.x * 256 + threadIdx.x;
    if (g >= BATCH * NW) return;
    int b = g >> 10, w = g & (NW - 1);
    int wy = w >> 5, wx = w & 31;

    u64 xv2[32];
#pragma unroll
    for (int qy = 0; qy < 8; qy++) {
        const u64* r = (const u64*)(g_xm + b * HW + (wy * 8 + qy) * 256 + wx * 8);
#pragma unroll
        for (int i = 0; i < 4; i++) xv2[qy * 4 + i] = r[i];
    }
    const u64* m1 = (const u64*)m1W;
    float z[8];
#pragma unroll
    for (int j = 0; j < 8; j++) {
        const u64* w1 = &m1[j * 32];
        u64 a0 = 0, a1 = 0;
#pragma unroll
        for (int i = 0; i < 32; i += 2) {
            a0 = fma2(xv2[i],   w1[i],   a0);
            a1 = fma2(xv2[i+1], w1[i+1], a1);
        }
        float a = m1b[j] + hadd2(a0) + hadd2(a1);
        z[j] = (a >= 0.f) ? a : 0.1f * a;
    }
    float l0 = m2b[0], l1 = m2b[1];
#pragma unroll
    for (int j = 0; j < 8; j++) { l0 += z[j] * m2W[j]; l1 += z[j] * m2W[8 + j]; }
    float mm = fmaxf(l0, l1);
    float e0 = __expf(l0 - mm), e1 = __expf(l1 - mm);
    g_score[g] = e0 / (e0 + e1);
}

// ---------------- K5: deterministic rank -> top-512 selection ----------------
__global__ __launch_bounds__(1024) void k_rank()
{
    __shared__ float s[NW];
    int b = blockIdx.x;
    int i = threadIdx.x;
    s[i] = g_score[b * NW + i];
    __syncthreads();
    float si = s[i];
    int r = 0;
    for (int j = 0; j < NW; j++) {
        float sj = s[j];
        r += (sj > si) || (sj == si && j < i);   // stable argsort(-score) tie-break
    }
    if (r < KEEP) {
        g_hard[b * KEEP + r] = i;
        g_ishard[b * NW + i] = 1;
    } else {
        g_ishard[b * NW + i] = 0;
    }
}

// ---------------- K6: windowed attention, FFMA2 + max-only pass1 ----------------
__global__ __launch_bounds__(64) void k_attn(
    const float* __restrict__ relh, const float* __restrict__ relw)
{
    __shared__ u64 ksh[144*8];     // K pre-scaled by 0.25, d-pairs
    __shared__ u64 vsh[144*8];
    __shared__ u64 srw[23*8];      // rel tables pre-scaled by 0.25
    __shared__ u64 srh[23*8];

    int t = threadIdx.x;                 // q token 0..63
    int b = blockIdx.x >> 9;
    int w = g_hard[blockIdx.x];
    int h = blockIdx.y;
    int wy = w >> 5, wx = w & 31;

    u64 s2 = pack2(0.25f, 0.25f);        // DH^-0.5, DH=16
    const u64* rw64 = (const u64*)relw;
    const u64* rh64 = (const u64*)relh;
    for (int i = t; i < 184; i += 64) {
        srw[i] = mul2(rw64[i], s2);
        srh[i] = mul2(rh64[i], s2);
    }

    int y0 = wy * 8 - 2, x0 = wx * 8 - 2;
    for (int kk = t; kk < 144; kk += 64) {
        int ky = kk / 12, kx = kk - ky * 12;
        int yy = y0 + ky, xx = x0 + kx;
        u64* kd = &ksh[kk * 8];
        u64* vd = &vsh[kk * 8];
        if ((unsigned)yy < 256u && (unsigned)xx < 256u) {
            size_t base = ((size_t)(b * HW + yy * 256 + xx)) * 64 + h * 16;
            const u64* kp = (const u64*)(g_k + base);
            const u64* vp = (const u64*)(g_v + base);
#pragma unroll
            for (int i = 0; i < 8; i++) { kd[i] = mul2(kp[i], s2); vd[i] = vp[i]; }
        } else {
#pragma unroll
            for (int i = 0; i < 8; i++) { kd[i] = 0ull; vd[i] = 0ull; }
        }
    }
    __syncthreads();

    int qy = t >> 3, qx = t & 7;
    size_t qbase = ((size_t)(b * HW + (wy * 8 + qy) * 256 + (wx * 8 + qx))) * 64 + h * 16;
    u64 q2[8];
    const u64* qp = (const u64*)(g_q + qbase);
#pragma unroll
    for (int i = 0; i < 8; i++) q2[i] = qp[i];

    // per-column / per-row relative bias (already scaled)
    float rwv[12], rhv[12];
#pragma unroll
    for (int k2 = 0; k2 < 12; k2++) {
        const u64* pw = &srw[(k2 - qx + 11) * 8];
        const u64* ph = &srh[(k2 - qy + 11) * 8];
        u64 a0 = 0, a1 = 0, c0 = 0, c1 = 0;
#pragma unroll
        for (int i = 0; i < 8; i += 2) {
            a0 = fma2(q2[i],   pw[i],   a0);
            a1 = fma2(q2[i+1], pw[i+1], a1);
            c0 = fma2(q2[i],   ph[i],   c0);
            c1 = fma2(q2[i+1], ph[i+1], c1);
        }
        rwv[k2] = hadd2(a0) + hadd2(a1);
        rhv[k2] = hadd2(c0) + hadd2(c1);
    }

    // pass 1: row max only (no exp)
    float m = -1e30f;
    for (int ky = 0; ky < 12; ky++) {
        float rh2 = rhv[ky];
#pragma unroll
        for (int kx = 0; kx < 12; kx++) {
            const u64* kr = &ksh[(ky * 12 + kx) * 8];
            u64 a0 = 0, a1 = 0;
#pragma unroll
            for (int i = 0; i < 8; i += 2) {
                a0 = fma2(q2[i],   kr[i],   a0);
                a1 = fma2(q2[i+1], kr[i+1], a1);
            }
            float l = hadd2(a0) + hadd2(a1) + rwv[kx] + rh2;
            m = fmaxf(m, l);
        }
    }

    // pass 2: recompute, exp, unnormalized V accumulation
    float sum = 0.f;
    u64 acc[8] = {0,0,0,0,0,0,0,0};
    for (int ky = 0; ky < 12; ky++) {
        float rh2 = rhv[ky];
#pragma unroll
        for (int kx = 0; kx < 12; kx++) {
            int kk = ky * 12 + kx;
            const u64* kr = &ksh[kk * 8];
            u64 a0 = 0, a1 = 0;
#pragma unroll
            for (int i = 0; i < 8; i += 2) {
                a0 = fma2(q2[i],   kr[i],   a0);
                a1 = fma2(q2[i+1], kr[i+1], a1);
            }
            float l = hadd2(a0) + hadd2(a1) + rwv[kx] + rh2;
            float wg = __expf(l - m);
            sum += wg;
            u64 w2 = pack2(wg, wg);
            const u64* vr = &vsh[kk * 8];
#pragma unroll
            for (int i = 0; i < 8; i++) acc[i] = fma2(w2, vr[i], acc[i]);
        }
    }
    float inv = 1.0f / sum;
    u64 inv2 = pack2(inv, inv);
    u64* op = (u64*)(g_mix + qbase);
#pragma unroll
    for (int i = 0; i < 8; i++) op[i] = mul2(acc[i], inv2);
}

// ---------------- K7: final 1x1 conv with easy/hard select, FFMA2 ----------------
__global__ __launch_bounds__(128) void k_final(
    const float* __restrict__ Wout, const float* __restrict__ bout,
    float* __restrict__ out)
{
    __shared__ u64 sw[2048];   // 16 KB, [oc][icpair] natural layout
    __shared__ float sb[64];
    const u64* w64 = (const u64*)Wout;
    for (int i = threadIdx.x; i < 2048; i += 128) sw[i] = w64[i];
    if (threadIdx.x < 64) sb[threadIdx.x] = bout[threadIdx.x];
    __syncthreads();

    int g = blockIdx.x * 128 + threadIdx.x;
    int b = g >> 16, p = g & (HW - 1);
    int y = p >> 8, x = p & 255;
    int w = (y >> 3) * 32 + (x >> 3);

    u64 mv2[32];
    if (g_ishard[b * NW + w]) {
        const u64* mp = (const u64*)(g_mix + (size_t)g * 64);
#pragma unroll
        for (int i = 0; i < 32; i++) mv2[i] = mp[i];
    } else {
        float s = g_sa[g];
        u64 ss = pack2(s, s);
        const u64* vp = (const u64*)(g_v + (size_t)g * 64);
#pragma unroll
        for (int i = 0; i < 32; i++) mv2[i] = mul2(vp[i], ss);
    }

    float* ob = out + (size_t)b * 64 * HW + p;
    for (int oc = 0; oc < 64; oc++) {
        const u64* wr = &sw[oc * 32];
        u64 a0 = 0, a1 = 0;
#pragma unroll
        for (int i = 0; i < 32; i += 2) {
            a0 = fma2(mv2[i],   wr[i],   a0);
            a1 = fma2(mv2[i+1], wr[i+1], a1);
        }
        ob[(size_t)oc * HW] = sb[oc] + hadd2(a0) + hadd2(a1);
    }
}

// ---------------- launch ----------------
extern "C" void kernel_launch(void* const* d_in, const int* in_sizes, int n_in,
                              void* d_out, int out_size)
{
    const float* x    = (const float*)d_in[0];
    const float* cg   = (const float*)d_in[1];
    const float* Wq   = (const float*)d_in[2];
    const float* bq   = (const float*)d_in[3];
    const float* Wk   = (const float*)d_in[4];
    const float* bk   = (const float*)d_in[5];
    const float* Wv   = (const float*)d_in[6];
    const float* bv   = (const float*)d_in[7];
    const float* Wout = (const float*)d_in[8];
    const float* bout = (const float*)d_in[9];
    const float* relh = (const float*)d_in[10];
    const float* relw = (const float*)d_in[11];
    const float* pinW = (const float*)d_in[12];
    const float* pinb = (const float*)d_in[13];
    const float* lnw  = (const float*)d_in[14];
    const float* lnb  = (const float*)d_in[15];
    const float* saW  = (const float*)d_in[16];
    const float* sab  = (const float*)d_in[17];
    const float* m1W  = (const float*)d_in[18];
    const float* m1b  = (const float*)d_in[19];
    const float* m2W  = (const float*)d_in[20];
    const float* m2b  = (const float*)d_in[21];
    float* out = (float*)d_out;

    k_qkv  <<<NPIX / 128, 128>>>(x, Wq, bq, Wk, bk, Wv, bv);
    k_pin  <<<NPIX / 256, 256>>>(cg, pinW, pinb, lnw, lnb);
    k_sa   <<<NPIX / 256, 256>>>(saW, sab);
    k_score<<<(BATCH * NW) / 256, 256>>>(m1W, m1b, m2W, m2b);
    k_rank <<<BATCH, 1024>>>();
    k_attn <<<dim3(BATCH * KEEP, 4), 64>>>(relh, relw);
    k_final<<<NPIX / 128, 128>>>(Wout, bout, out);
}

// round 3
// speedup vs baseline: 1.3507x; 1.2700x over previous
#include <cuda_runtime.h>
#include <math.h>

#define HW 65536            // 256*256
#define BATCH 2
#define NPIX (BATCH*HW)     // 131072
#define NW 1024             // windows per batch (32x32)
#define KEEP 512

typedef unsigned long long u64;

// ---------------- packed f32x2 helpers (Blackwell) ----------------
__device__ __forceinline__ u64 fma2(u64 a, u64 b, u64 c) {
    u64 d; asm("fma.rn.f32x2 %0,%1,%2,%3;" : "=l"(d) : "l"(a), "l"(b), "l"(c)); return d;
}
__device__ __forceinline__ u64 mul2(u64 a, u64 b) {
    u64 d; asm("mul.rn.f32x2 %0,%1,%2;" : "=l"(d) : "l"(a), "l"(b)); return d;
}
__device__ __forceinline__ u64 pack2(float lo, float hi) {
    u64 r; asm("mov.b64 %0,{%1,%2};" : "=l"(r) : "f"(lo), "f"(hi)); return r;
}
__device__ __forceinline__ float hadd2(u64 v) {
    float lo, hi; asm("mov.b64 {%0,%1},%2;" : "=f"(lo), "=f"(hi) : "l"(v)); return lo + hi;
}

// ---------------- scratch ----------------
__device__ float g_q[NPIX*64];     // NHWC
__device__ float g_k[NPIX*64];     // NHWC
__device__ float g_v[NPIX*64];     // NHWC
__device__ float g_mix[NPIX*64];   // NHWC
__device__ float g_h1p[17*NPIX];   // planar [c][pix]
__device__ float g_sa[NPIX];
__device__ float g_xm[NPIX];
__device__ float g_score[BATCH*NW];
__device__ int   g_hard[BATCH*KEEP];
__device__ int   g_ishard[BATCH*NW];

// ======================= K1: qkv as tiled GEMM =======================
// grid 1024 (128 px/tile), block 256. dyn smem: u64 sw2[3*2048] + u64 sx2[64*128]
__global__ __launch_bounds__(256) void k_qkv(
    const float* __restrict__ x,
    const float* __restrict__ Wq, const float* __restrict__ bq,
    const float* __restrict__ Wk, const float* __restrict__ bk,
    const float* __restrict__ Wv, const float* __restrict__ bv)
{
    extern __shared__ __align__(16) char dyn[];
    u64* sw2 = (u64*)dyn;             // [mat][ic][ocpair] = (W[2j][ic], W[2j+1][ic])
    u64* sx2 = sw2 + 3*2048;          // [ic][px] = (x,x)

    int t = threadIdx.x;
    int p0 = blockIdx.x * 128;
    int b  = p0 >> 16, p = p0 & (HW - 1);

    for (int e = t; e < 6144; e += 256) {
        int m = e >> 11, r = e & 2047, ic = r >> 5, j = r & 31;
        const float* W = (m == 0) ? Wq : (m == 1) ? Wk : Wv;
        sw2[e] = pack2(W[(2*j)*64 + ic], W[(2*j+1)*64 + ic]);
    }
    const float* xb = x + (size_t)b * 64 * HW + p;
#pragma unroll
    for (int i = 0; i < 8; i++) {
        int fidx = i * 256 + t;          // 2048 float4
        int ic = fidx >> 5, c4 = fidx & 31;
        float4 v = *(const float4*)(xb + (size_t)ic * HW + 4 * c4);
        u64* row = &sx2[ic * 128 + 4 * c4];
        row[0] = pack2(v.x, v.x); row[1] = pack2(v.y, v.y);
        row[2] = pack2(v.z, v.z); row[3] = pack2(v.w, v.w);
    }
    __syncthreads();

    int jA = t & 15, jB = jA + 16, pxb = t >> 4;

#pragma unroll
    for (int m = 0; m < 3; m++) {
        const u64* W = &sw2[m * 2048];
        const float* bs = (m == 0) ? bq : (m == 1) ? bk : bv;
        float* gX = (m == 0) ? g_q : (m == 1) ? g_k : g_v;

        u64 biasA = pack2(bs[2*jA], bs[2*jA+1]);
        u64 biasB = pack2(bs[2*jB], bs[2*jB+1]);
        u64 accA[8], accB[8];
#pragma unroll
        for (int k = 0; k < 8; k++) { accA[k] = biasA; accB[k] = biasB; }

#pragma unroll 4
        for (int ic = 0; ic < 64; ic++) {
            u64 wA = W[ic * 32 + jA];
            u64 wB = W[ic * 32 + jB];
            const u64* xr = &sx2[ic * 128 + pxb];
#pragma unroll
            for (int k = 0; k < 8; k++) {
                u64 xv = xr[16 * k];
                accA[k] = fma2(xv, wA, accA[k]);
                accB[k] = fma2(xv, wB, accB[k]);
            }
        }
#pragma unroll
        for (int k = 0; k < 8; k++) {
            int px = pxb + 16 * k;
            u64* o = (u64*)(gX + (size_t)(p0 + px) * 64);
            o[jA] = accA[k]; o[jB] = accB[k];
        }
    }
}

// ======================= K2: pin conv + LN + lrelu + xm =======================
// block 128 (1 px/thread), v rows staged via smem coalesced; h1 stored planar.
__global__ __launch_bounds__(128) void k_pin(
    const float* __restrict__ cg,
    const float* __restrict__ pinW, const float* __restrict__ pinb,
    const float* __restrict__ lnw,  const float* __restrict__ lnb)
{
    __shared__ float vt[128][66];
    __shared__ u64 sw2[17*34];
    __shared__ float sb[17], slw[17], slb[17];

    int t = threadIdx.x;
    int p0 = blockIdx.x * 128;

    const u64* pw64 = (const u64*)pinW;
    for (int i = t; i < 17*34; i += 128) sw2[i] = pw64[i];
    if (t < 17) { sb[t] = pinb[t]; slw[t] = lnw[t]; slb[t] = lnb[t]; }

#pragma unroll
    for (int i = 0; i < 16; i++) {
        int fidx = i * 128 + t;           // 2048 float4 = 128 rows x 16
        int row = fidx >> 4, c4 = fidx & 15;
        float4 v = *(const float4*)(g_v + (size_t)(p0 + row) * 64 + 4 * c4);
        vt[row][4*c4+0] = v.x; vt[row][4*c4+1] = v.y;
        vt[row][4*c4+2] = v.z; vt[row][4*c4+3] = v.w;
    }
    __syncthreads();

    int g = p0 + t;
    int b = g >> 16, p = g & (HW - 1);
    int y = p >> 8, xx = p & 255;

    u64 c2[34];
    const u64* vrow = (const u64*)&vt[t][0];
#pragma unroll
    for (int i = 0; i < 32; i++) c2[i] = vrow[i];
    c2[32] = pack2(cg[(size_t)b * 2 * HW + p], cg[(size_t)b * 2 * HW + HW + p]);
    c2[33] = pack2(-1.0f + (2.0f / 7.0f) * (float)(y & 7),
                   -1.0f + (2.0f / 7.0f) * (float)(xx & 7));

    float h[17];
    for (int oc = 0; oc < 17; oc++) {
        const u64* w = &sw2[oc * 34];
        u64 a0 = 0, a1 = 0;
#pragma unroll
        for (int i = 0; i < 34; i += 2) {
            a0 = fma2(c2[i],   w[i],   a0);
            a1 = fma2(c2[i+1], w[i+1], a1);
        }
        h[oc] = sb[oc] + hadd2(a0) + hadd2(a1);
    }
    float u = 0.f;
#pragma unroll
    for (int oc = 0; oc < 17; oc++) u += h[oc];
    u *= (1.0f / 17.0f);
    float sv = 0.f;
#pragma unroll
    for (int oc = 0; oc < 17; oc++) { float d = h[oc] - u; sv += d * d; }
    sv *= (1.0f / 17.0f);
    float inv = rsqrtf(sv + 1e-6f);

    float xs = 0.f;
#pragma unroll
    for (int oc = 0; oc < 17; oc++) {
        float tv = slw[oc] * (h[oc] - u) * inv + slb[oc];
        tv = (tv >= 0.f) ? tv : 0.1f * tv;
        g_h1p[(size_t)oc * NPIX + g] = tv;    // planar, coalesced
        xs += tv;
    }
    g_xm[g] = xs * (1.0f / 17.0f);
}

// ======================= K3: 3x3 conv (17->1) + sigmoid, planar =======================
__global__ __launch_bounds__(256) void k_sa(
    const float* __restrict__ saW, const float* __restrict__ sab)
{
    __shared__ float swt[153];
    for (int i = threadIdx.x; i < 153; i += 256) swt[i] = saW[i];
    __syncthreads();
    int g = blockIdx.x * 256 + threadIdx.x;
    int b = g >> 16, p = g & (HW - 1);
    int y = p >> 8, x = p & 255;
    float acc = sab[0];
#pragma unroll
    for (int c = 0; c < 17; c++) {
        const float* plane = g_h1p + (size_t)c * NPIX + (size_t)b * HW;
        const float* wr = &swt[c * 9];
#pragma unroll
        for (int dy = -1; dy <= 1; dy++) {
            int yy = y + dy;
            if ((unsigned)yy > 255u) continue;
#pragma unroll
            for (int dx = -1; dx <= 1; dx++) {
                int xxp = x + dx;
                if ((unsigned)xxp > 255u) continue;
                acc += plane[yy * 256 + xxp] * wr[(dy + 1) * 3 + (dx + 1)];
            }
        }
    }
    g_sa[g] = 1.0f / (1.0f + __expf(-acc));
}

// ======================= K4: window score MLP + softmax =======================
__global__ __launch_bounds__(256) void k_score(
    const float* __restrict__ m1W, const float* __restrict__ m1b,
    const float* __restrict__ m2W, const float* __restrict__ m2b)
{
    int g = blockIdx.x * 256 + threadIdx.x;
    if (g >= BATCH * NW) return;
    int b = g >> 10, w = g & (NW - 1);
    int wy = w >> 5, wx = w & 31;

    u64 xv2[32];
#pragma unroll
    for (int qy = 0; qy < 8; qy++) {
        const u64* r = (const u64*)(g_xm + b * HW + (wy * 8 + qy) * 256 + wx * 8);
#pragma unroll
        for (int i = 0; i < 4; i++) xv2[qy * 4 + i] = r[i];
    }
    const u64* m1 = (const u64*)m1W;
    float z[8];
#pragma unroll
    for (int j = 0; j < 8; j++) {
        const u64* w1 = &m1[j * 32];
        u64 a0 = 0, a1 = 0;
#pragma unroll
        for (int i = 0; i < 32; i += 2) {
            a0 = fma2(xv2[i],   w1[i],   a0);
            a1 = fma2(xv2[i+1], w1[i+1], a1);
        }
        float a = m1b[j] + hadd2(a0) + hadd2(a1);
        z[j] = (a >= 0.f) ? a : 0.1f * a;
    }
    float l0 = m2b[0], l1 = m2b[1];
#pragma unroll
    for (int j = 0; j < 8; j++) { l0 += z[j] * m2W[j]; l1 += z[j] * m2W[8 + j]; }
    float mm = fmaxf(l0, l1);
    float e0 = __expf(l0 - mm), e1 = __expf(l1 - mm);
    g_score[g] = e0 / (e0 + e1);
}

// ======================= K5: deterministic rank -> top-512 =======================
__global__ __launch_bounds__(1024) void k_rank()
{
    __shared__ float s[NW];
    int b = blockIdx.x;
    int i = threadIdx.x;
    s[i] = g_score[b * NW + i];
    __syncthreads();
    float si = s[i];
    int r = 0;
    for (int j = 0; j < NW; j++) {
        float sj = s[j];
        r += (sj > si) || (sj == si && j < i);
    }
    if (r < KEEP) {
        g_hard[b * KEEP + r] = i;
        g_ishard[b * NW + i] = 1;
    } else {
        g_ishard[b * NW + i] = 0;
    }
}

// ======================= K6: attention, 1 block per window (4 heads merged) =======================
// dyn smem: float ks[144*64]; float vs[144*64]; float qs[64*68]; u64 srw[184]; u64 srh[184]
#define ATTN_SMEM (144*64*4*2 + 64*68*4 + 184*8*2)
__global__ __launch_bounds__(256) void k_attn(
    const float* __restrict__ relh, const float* __restrict__ relw)
{
    extern __shared__ __align__(16) char dyn[];
    float* ks = (float*)dyn;                 // pre-scaled by 0.25
    float* vs = ks + 144*64;
    float* qs = vs + 144*64;                 // [64][68]
    u64* srw  = (u64*)(qs + 64*68);
    u64* srh  = srw + 184;

    int t = threadIdx.x;
    int head = t >> 6, tok = t & 63;
    int b = blockIdx.x >> 9;
    int w = g_hard[blockIdx.x];
    int wy = w >> 5, wx = w & 31;

    u64 s2 = pack2(0.25f, 0.25f);
    const u64* rw64 = (const u64*)relw;
    const u64* rh64 = (const u64*)relh;
    for (int i = t; i < 184; i += 256) {
        srw[i] = mul2(rw64[i], s2);
        srh[i] = mul2(rh64[i], s2);
    }

    int y0 = wy * 8 - 2, x0 = wx * 8 - 2;
#pragma unroll
    for (int i = 0; i < 9; i++) {
        int fidx = i * 256 + t;              // 2304 float4 = 144 rows x 16
        int kk = fidx >> 4, c4 = fidx & 15;
        int yy = y0 + kk / 12, xxp = x0 + kk % 12;
        float4 kv = make_float4(0.f, 0.f, 0.f, 0.f), vv = kv;
        if ((unsigned)yy < 256u && (unsigned)xxp < 256u) {
            size_t base = ((size_t)(b * HW + yy * 256 + xxp)) * 64 + 4 * c4;
            kv = *(const float4*)(g_k + base);
            vv = *(const float4*)(g_v + base);
            kv.x *= 0.25f; kv.y *= 0.25f; kv.z *= 0.25f; kv.w *= 0.25f;
        }
        *(float4*)(ks + kk * 64 + 4 * c4) = kv;
        *(float4*)(vs + kk * 64 + 4 * c4) = vv;
    }
#pragma unroll
    for (int i = 0; i < 4; i++) {
        int fidx = i * 256 + t;              // 1024 float4 = 64 rows x 16
        int tk = fidx >> 4, c4 = fidx & 15;
        int py = wy * 8 + (tk >> 3), px = wx * 8 + (tk & 7);
        float4 qv = *(const float4*)(g_q + ((size_t)(b * HW + py * 256 + px)) * 64 + 4 * c4);
        *(float4*)(qs + tk * 68 + 4 * c4) = qv;
    }
    __syncthreads();

    u64 q2[8];
    const u64* qrow = (const u64*)(qs + tok * 68 + head * 16);
#pragma unroll
    for (int i = 0; i < 8; i++) q2[i] = qrow[i];

    int qy = tok >> 3, qx = tok & 7;

    float rwv[12], rhv[12];
#pragma unroll
    for (int k2 = 0; k2 < 12; k2++) {
        const u64* pw = &srw[(k2 - qx + 11) * 8];
        const u64* ph = &srh[(k2 - qy + 11) * 8];
        u64 a0 = 0, a1 = 0, c0 = 0, c1 = 0;
#pragma unroll
        for (int i = 0; i < 8; i += 2) {
            a0 = fma2(q2[i],   pw[i],   a0);
            a1 = fma2(q2[i+1], pw[i+1], a1);
            c0 = fma2(q2[i],   ph[i],   c0);
            c1 = fma2(q2[i+1], ph[i+1], c1);
        }
        rwv[k2] = hadd2(a0) + hadd2(a1);
        rhv[k2] = hadd2(c0) + hadd2(c1);
    }

    // pass 1: max only
    float m = -1e30f;
    for (int ky = 0; ky < 12; ky++) {
        float rh2 = rhv[ky];
#pragma unroll
        for (int kx = 0; kx < 12; kx++) {
            const u64* kr = (const u64*)(ks + (ky * 12 + kx) * 64 + head * 16);
            u64 a0 = 0, a1 = 0;
#pragma unroll
            for (int i = 0; i < 8; i += 2) {
                a0 = fma2(q2[i],   kr[i],   a0);
                a1 = fma2(q2[i+1], kr[i+1], a1);
            }
            float l = hadd2(a0) + hadd2(a1) + rwv[kx] + rh2;
            m = fmaxf(m, l);
        }
    }

    // pass 2: recompute, exp, accumulate
    float sum = 0.f;
    u64 acc[8] = {0,0,0,0,0,0,0,0};
    for (int ky = 0; ky < 12; ky++) {
        float rh2 = rhv[ky];
#pragma unroll
        for (int kx = 0; kx < 12; kx++) {
            int kk = ky * 12 + kx;
            const u64* kr = (const u64*)(ks + kk * 64 + head * 16);
            u64 a0 = 0, a1 = 0;
#pragma unroll
            for (int i = 0; i < 8; i += 2) {
                a0 = fma2(q2[i],   kr[i],   a0);
                a1 = fma2(q2[i+1], kr[i+1], a1);
            }
            float l = hadd2(a0) + hadd2(a1) + rwv[kx] + rh2;
            float wg = __expf(l - m);
            sum += wg;
            u64 w2 = pack2(wg, wg);
            const u64* vr = (const u64*)(vs + kk * 64 + head * 16);
#pragma unroll
            for (int i = 0; i < 8; i++) acc[i] = fma2(w2, vr[i], acc[i]);
        }
    }
    float invs = 1.0f / sum;
    u64 inv2 = pack2(invs, invs);
    u64* oq = (u64*)(qs + tok * 68 + head * 16);   // reuse qs as output stage
#pragma unroll
    for (int i = 0; i < 8; i++) oq[i] = mul2(acc[i], inv2);
    __syncthreads();

#pragma unroll
    for (int i = 0; i < 4; i++) {
        int fidx = i * 256 + t;
        int tk = fidx >> 4, c4 = fidx & 15;
        int py = wy * 8 + (tk >> 3), px = wx * 8 + (tk & 7);
        float4 ov = *(const float4*)(qs + tk * 68 + 4 * c4);
        *(float4*)(g_mix + ((size_t)(b * HW + py * 256 + px)) * 64 + 4 * c4) = ov;
    }
}

// ======================= K7: final 1x1 conv as tiled GEMM (NCHW out) =======================
// dyn smem: u64 swb[64*64] (w broadcast pairs) + float sx[64*130] (px-major, padded)
#define FINAL_SMEM (64*64*8 + 64*130*4)
__global__ __launch_bounds__(256) void k_final(
    const float* __restrict__ Wout, const float* __restrict__ bout,
    float* __restrict__ out)
{
    extern __shared__ __align__(16) char dyn[];
    u64* swb = (u64*)dyn;                 // [ic][oc] = (w,w)
    float* sx = (float*)(swb + 64*64);    // [ic][130], px pairs read as u64

    int t = threadIdx.x;
    int p0 = blockIdx.x * 128;
    int bb = p0 >> 16, ploc = p0 & (HW - 1);

    for (int e = t; e < 4096; e += 256) {
        int ic = e >> 6, oc = e & 63;
        float wv = Wout[oc * 64 + ic];
        swb[e] = pack2(wv, wv);
    }
#pragma unroll
    for (int i = 0; i < 8; i++) {
        int fidx = i * 256 + t;            // 2048 float4 = 128 px x 16
        int px = fidx >> 4, c4 = fidx & 15;
        int g = p0 + px;
        int p = g & (HW - 1);
        int wdw = ((p >> 11) << 5) | ((p >> 3) & 31);
        float4 v;
        if (g_ishard[(g >> 16) * NW + wdw]) {
            v = *(const float4*)(g_mix + (size_t)g * 64 + 4 * c4);
        } else {
            v = *(const float4*)(g_v + (size_t)g * 64 + 4 * c4);
            float s = g_sa[g];
            v.x *= s; v.y *= s; v.z *= s; v.w *= s;
        }
        float* col = sx + (4 * c4) * 130 + px;
        col[0]   = v.x; col[130] = v.y; col[260] = v.z; col[390] = v.w;
    }
    __syncthreads();

    int o = t >> 4;          // oc base: oc = o + 16a
    int pp = t & 15;         // px pair:  pair = pp + 16b2

    u64 acc[4][4];
#pragma unroll
    for (int a = 0; a < 4; a++) {
        float bb2 = bout[o + 16 * a];
        u64 bi = pack2(bb2, bb2);
#pragma unroll
        for (int c = 0; c < 4; c++) acc[a][c] = bi;
    }

#pragma unroll 4
    for (int ic = 0; ic < 64; ic++) {
        const u64* xr = (const u64*)(sx + ic * 130) + pp;
        u64 x0 = xr[0], x1 = xr[16], x2 = xr[32], x3 = xr[48];
        const u64* wr = &swb[ic * 64 + o];
#pragma unroll
        for (int a = 0; a < 4; a++) {
            u64 wv = wr[16 * a];
            acc[a][0] = fma2(x0, wv, acc[a][0]);
            acc[a][1] = fma2(x1, wv, acc[a][1]);
            acc[a][2] = fma2(x2, wv, acc[a][2]);
            acc[a][3] = fma2(x3, wv, acc[a][3]);
        }
    }

#pragma unroll
    for (int a = 0; a < 4; a++) {
        int oc = o + 16 * a;
        u64* obase = (u64*)(out + (size_t)bb * 64 * HW + (size_t)oc * HW + ploc);
#pragma unroll
        for (int c = 0; c < 4; c++) obase[pp + 16 * c] = acc[a][c];
    }
}

// ======================= launch =======================
extern "C" void kernel_launch(void* const* d_in, const int* in_sizes, int n_in,
                              void* d_out, int out_size)
{
    const float* x    = (const float*)d_in[0];
    const float* cg   = (const float*)d_in[1];
    const float* Wq   = (const float*)d_in[2];
    const float* bq   = (const float*)d_in[3];
    const float* Wk   = (const float*)d_in[4];
    const float* bk   = (const float*)d_in[5];
    const float* Wv   = (const float*)d_in[6];
    const float* bv   = (const float*)d_in[7];
    const float* Wout = (const float*)d_in[8];
    const float* bout = (const float*)d_in[9];
    const float* relh = (const float*)d_in[10];
    const float* relw = (const float*)d_in[11];
    const float* pinW = (const float*)d_in[12];
    const float* pinb = (const float*)d_in[13];
    const float* lnw  = (const float*)d_in[14];
    const float* lnb  = (const float*)d_in[15];
    const float* saW  = (const float*)d_in[16];
    const float* sab  = (const float*)d_in[17];
    const float* m1W  = (const float*)d_in[18];
    const float* m1b  = (const float*)d_in[19];
    const float* m2W  = (const float*)d_in[20];
    const float* m2b  = (const float*)d_in[21];
    float* out = (float*)d_out;

    const int QKV_SMEM = 3*2048*8 + 64*128*8;   // 114688
    cudaFuncSetAttribute(k_qkv,   cudaFuncAttributeMaxDynamicSharedMemorySize, QKV_SMEM);
    cudaFuncSetAttribute(k_attn,  cudaFuncAttributeMaxDynamicSharedMemorySize, ATTN_SMEM);
    cudaFuncSetAttribute(k_final, cudaFuncAttributeMaxDynamicSharedMemorySize, FINAL_SMEM);

    k_qkv  <<<NPIX / 128, 256, QKV_SMEM>>>(x, Wq, bq, Wk, bk, Wv, bv);
    k_pin  <<<NPIX / 128, 128>>>(cg, pinW, pinb, lnw, lnb);
    k_sa   <<<NPIX / 256, 256>>>(saW, sab);
    k_score<<<(BATCH * NW) / 256, 256>>>(m1W, m1b, m2W, m2b);
    k_rank <<<BATCH, 1024>>>();
    k_attn <<<BATCH * KEEP, 256, ATTN_SMEM>>>(relh, relw);
    k_final<<<NPIX / 128, 256, FINAL_SMEM>>>(Wout, bout, out);
}

// round 4
// speedup vs baseline: 1.6544x; 1.2248x over previous
#include <cuda_runtime.h>
#include <math.h>

#define HW 65536            // 256*256
#define BATCH 2
#define NPIX (BATCH*HW)     // 131072
#define NW 1024
#define KEEP 512

typedef unsigned long long u64;
typedef unsigned int u32;

// ---------------- packed f32x2 helpers ----------------
__device__ __forceinline__ u64 fma2(u64 a, u64 b, u64 c) {
    u64 d; asm("fma.rn.f32x2 %0,%1,%2,%3;" : "=l"(d) : "l"(a), "l"(b), "l"(c)); return d;
}
__device__ __forceinline__ u64 mul2(u64 a, u64 b) {
    u64 d; asm("mul.rn.f32x2 %0,%1,%2;" : "=l"(d) : "l"(a), "l"(b)); return d;
}
__device__ __forceinline__ u64 add2(u64 a, u64 b) {
    u64 d; asm("add.rn.f32x2 %0,%1,%2;" : "=l"(d) : "l"(a), "l"(b)); return d;
}
__device__ __forceinline__ u64 pack2(float lo, float hi) {
    u64 r; asm("mov.b64 %0,{%1,%2};" : "=l"(r) : "f"(lo), "f"(hi)); return r;
}
__device__ __forceinline__ float hadd2(u64 v) {
    float lo, hi; asm("mov.b64 {%0,%1},%2;" : "=f"(lo), "=f"(hi) : "l"(v)); return lo + hi;
}
__device__ __forceinline__ float lo2(u64 v) {
    float lo, hi; asm("mov.b64 {%0,%1},%2;" : "=f"(lo), "=f"(hi) : "l"(v)); return lo;
}
__device__ __forceinline__ float hi2(u64 v) {
    float lo, hi; asm("mov.b64 {%0,%1},%2;" : "=f"(lo), "=f"(hi) : "l"(v)); return hi;
}

// ---------------- tf32 helpers ----------------
__device__ __forceinline__ void tf32split(float x, u32& h, u32& l) {
    asm("cvt.rna.tf32.f32 %0,%1;" : "=r"(h) : "f"(x));
    float r = x - __uint_as_float(h);
    asm("cvt.rna.tf32.f32 %0,%1;" : "=r"(l) : "f"(r));
}
__device__ __forceinline__ void mma8(float* d, const u32* a, const u32* b) {
    asm volatile("mma.sync.aligned.m16n8k8.row.col.f32.tf32.tf32.f32 "
        "{%0,%1,%2,%3},{%4,%5,%6,%7},{%8,%9},{%0,%1,%2,%3};"
        : "+f"(d[0]), "+f"(d[1]), "+f"(d[2]), "+f"(d[3])
        : "r"(a[0]), "r"(a[1]), "r"(a[2]), "r"(a[3]), "r"(b[0]), "r"(b[1]));
}

// ---------------- scratch ----------------
__device__ float g_q[NPIX*64];     // NHWC
__device__ float g_k[NPIX*64];
__device__ float g_v[NPIX*64];
__device__ float g_mix[NPIX*64];
__device__ float g_h1p[17*NPIX];   // planar
__device__ float g_sa[NPIX];
__device__ float g_xm[NPIX];
__device__ float g_score[BATCH*NW];
__device__ int   g_hard[BATCH*KEEP];
__device__ int   g_ishard[BATCH*NW];

// ======================= K1: qkv via tf32 mma (3x split) =======================
// block 256 (8 warps), tile M=128px, N=192oc(q|k|v), K=64.
// smem: sAh/sAl [ic][136]px, sBh/sBl [oc192][68]ic; sC [px][196] overlaps.
#define QKV_SMEM ((64*136*2 + 192*68*2) * 4)
__global__ __launch_bounds__(256) void k_qkv(
    const float* __restrict__ x,
    const float* __restrict__ Wq, const float* __restrict__ bq,
    const float* __restrict__ Wk, const float* __restrict__ bk,
    const float* __restrict__ Wv, const float* __restrict__ bv)
{
    extern __shared__ __align__(16) u32 sm[];
    u32* sAh = sm;                    // [64][136]
    u32* sAl = sAh + 64*136;
    u32* sBh = sAl + 64*136;          // [192][68]
    u32* sBl = sBh + 192*68;
    float* sC = (float*)sm;           // [128][196]  (reused after k-loop)

    int t = threadIdx.x;
    int p0 = blockIdx.x * 128;
    int b  = p0 >> 16, p = p0 & (HW - 1);
    const float* xb = x + (size_t)b * 64 * HW + p;

    // stage x -> tf32 hi/lo, [ic][px]
#pragma unroll
    for (int i = 0; i < 8; i++) {
        int fidx = i * 256 + t;
        int ic = fidx >> 5, px4 = (fidx & 31) << 2;
        float4 v = *(const float4*)(xb + (size_t)ic * HW + px4);
        uint4 h, l;
        tf32split(v.x, h.x, l.x); tf32split(v.y, h.y, l.y);
        tf32split(v.z, h.z, l.z); tf32split(v.w, h.w, l.w);
        *(uint4*)(sAh + ic * 136 + px4) = h;
        *(uint4*)(sAl + ic * 136 + px4) = l;
    }
    // stage W -> tf32 hi/lo, [oc][ic], oc 0..191 = q|k|v
#pragma unroll
    for (int i = 0; i < 12; i++) {
        int widx = i * 256 + t;
        int oc = widx >> 4, ic4 = (widx & 15) << 2;
        const float* Wm = (oc < 64) ? Wq : (oc < 128) ? Wk : Wv;
        float4 v = *(const float4*)(Wm + (oc & 63) * 64 + ic4);
        uint4 h, l;
        tf32split(v.x, h.x, l.x); tf32split(v.y, h.y, l.y);
        tf32split(v.z, h.z, l.z); tf32split(v.w, h.w, l.w);
        *(uint4*)(sBh + oc * 68 + ic4) = h;
        *(uint4*)(sBl + oc * 68 + ic4) = l;
    }
    __syncthreads();

    int lane = t & 31, warp = t >> 5;
    int g = lane >> 2, i4 = lane & 3;
    int mg = warp >> 2, ng = warp & 3;    // 2 m-groups x 4 n-groups; warp: 4 m-tiles x 6 n-tiles

    float acc[4][6][4];
#pragma unroll
    for (int mt = 0; mt < 4; mt++)
#pragma unroll
        for (int nt = 0; nt < 6; nt++)
#pragma unroll
            for (int c = 0; c < 4; c++) acc[mt][nt][c] = 0.f;

#pragma unroll
    for (int kt = 0; kt < 8; kt++) {
        u32 ah[4][4], al[4][4];
#pragma unroll
        for (int mt = 0; mt < 4; mt++) {
            int mrow = mg * 64 + mt * 16 + g;
            const u32* pA = sAh + (kt * 8 + i4) * 136 + mrow;
            const u32* qA = sAl + (kt * 8 + i4) * 136 + mrow;
            ah[mt][0] = pA[0]; ah[mt][1] = pA[8]; ah[mt][2] = pA[4*136]; ah[mt][3] = pA[4*136+8];
            al[mt][0] = qA[0]; al[mt][1] = qA[8]; al[mt][2] = qA[4*136]; al[mt][3] = qA[4*136+8];
        }
        u32 bh[6][2], bl[6][2];
#pragma unroll
        for (int nt = 0; nt < 6; nt++) {
            int ocol = ng * 48 + nt * 8 + g;
            const u32* pB = sBh + ocol * 68 + kt * 8 + i4;
            const u32* qB = sBl + ocol * 68 + kt * 8 + i4;
            bh[nt][0] = pB[0]; bh[nt][1] = pB[4];
            bl[nt][0] = qB[0]; bl[nt][1] = qB[4];
        }
#pragma unroll
        for (int mt = 0; mt < 4; mt++)
#pragma unroll
            for (int nt = 0; nt < 6; nt++) {
                mma8(acc[mt][nt], ah[mt], bh[nt]);
                mma8(acc[mt][nt], ah[mt], bl[nt]);
                mma8(acc[mt][nt], al[mt], bh[nt]);
            }
    }
    __syncthreads();   // A/B dead; reuse as sC

#pragma unroll
    for (int mt = 0; mt < 4; mt++)
#pragma unroll
        for (int nt = 0; nt < 6; nt++) {
            int row = mg * 64 + mt * 16 + g;
            int col = ng * 48 + nt * 8 + 2 * i4;
            float* c = sC + row * 196 + col;
            c[0] = acc[mt][nt][0]; c[1] = acc[mt][nt][1];
            c += 8 * 196;
            c[0] = acc[mt][nt][2]; c[1] = acc[mt][nt][3];
        }
    __syncthreads();

    // cooperative bias + store, float4 coalesced NHWC
#pragma unroll
    for (int i = 0; i < 24; i++) {
        int fidx = i * 256 + t;           // mat*2048 + px*16 + c4
        int mat = fidx >> 11;
        int r = fidx & 2047;
        int px = r >> 4, c4 = (r & 15) << 2;
        float4 v = *(float4*)(sC + px * 196 + mat * 64 + c4);
        const float* bias = (mat == 0) ? bq : (mat == 1) ? bk : bv;
        float4 bv4 = *(const float4*)(bias + c4);
        v.x += bv4.x; v.y += bv4.y; v.z += bv4.z; v.w += bv4.w;
        float* gX = (mat == 0) ? g_q : (mat == 1) ? g_k : g_v;
        *(float4*)(gX + (size_t)(p0 + px) * 64 + c4) = v;
    }
}

// ======================= K2: pin conv + LN + lrelu + xm =======================
__global__ __launch_bounds__(128) void k_pin(
    const float* __restrict__ cg,
    const float* __restrict__ pinW, const float* __restrict__ pinb,
    const float* __restrict__ lnw,  const float* __restrict__ lnb)
{
    __shared__ float vt[128][66];
    __shared__ u64 sw2[17*34];
    __shared__ float sb[17], slw[17], slb[17];

    int t = threadIdx.x;
    int p0 = blockIdx.x * 128;

    const u64* pw64 = (const u64*)pinW;
    for (int i = t; i < 17*34; i += 128) sw2[i] = pw64[i];
    if (t < 17) { sb[t] = pinb[t]; slw[t] = lnw[t]; slb[t] = lnb[t]; }

#pragma unroll
    for (int i = 0; i < 16; i++) {
        int fidx = i * 128 + t;
        int row = fidx >> 4, c4 = fidx & 15;
        float4 v = *(const float4*)(g_v + (size_t)(p0 + row) * 64 + 4 * c4);
        vt[row][4*c4+0] = v.x; vt[row][4*c4+1] = v.y;
        vt[row][4*c4+2] = v.z; vt[row][4*c4+3] = v.w;
    }
    __syncthreads();

    int g = p0 + t;
    int b = g >> 16, p = g & (HW - 1);
    int y = p >> 8, xx = p & 255;

    u64 c2[34];
    const u64* vrow = (const u64*)&vt[t][0];
#pragma unroll
    for (int i = 0; i < 32; i++) c2[i] = vrow[i];
    c2[32] = pack2(cg[(size_t)b * 2 * HW + p], cg[(size_t)b * 2 * HW + HW + p]);
    c2[33] = pack2(-1.0f + (2.0f / 7.0f) * (float)(y & 7),
                   -1.0f + (2.0f / 7.0f) * (float)(xx & 7));

    float h[17];
    for (int oc = 0; oc < 17; oc++) {
        const u64* w = &sw2[oc * 34];
        u64 a0 = 0, a1 = 0;
#pragma unroll
        for (int i = 0; i < 34; i += 2) {
            a0 = fma2(c2[i],   w[i],   a0);
            a1 = fma2(c2[i+1], w[i+1], a1);
        }
        h[oc] = sb[oc] + hadd2(a0) + hadd2(a1);
    }
    float u = 0.f;
#pragma unroll
    for (int oc = 0; oc < 17; oc++) u += h[oc];
    u *= (1.0f / 17.0f);
    float sv = 0.f;
#pragma unroll
    for (int oc = 0; oc < 17; oc++) { float d = h[oc] - u; sv += d * d; }
    sv *= (1.0f / 17.0f);
    float inv = rsqrtf(sv + 1e-6f);

    float xs = 0.f;
#pragma unroll
    for (int oc = 0; oc < 17; oc++) {
        float tv = slw[oc] * (h[oc] - u) * inv + slb[oc];
        tv = (tv >= 0.f) ? tv : 0.1f * tv;
        g_h1p[(size_t)oc * NPIX + g] = tv;
        xs += tv;
    }
    g_xm[g] = xs * (1.0f / 17.0f);
}

// ======================= K3: 3x3 conv (17->1) + sigmoid =======================
__global__ __launch_bounds__(256) void k_sa(
    const float* __restrict__ saW, const float* __restrict__ sab)
{
    __shared__ float swt[153];
    for (int i = threadIdx.x; i < 153; i += 256) swt[i] = saW[i];
    __syncthreads();
    int g = blockIdx.x * 256 + threadIdx.x;
    int b = g >> 16, p = g & (HW - 1);
    int y = p >> 8, x = p & 255;
    float acc = sab[0];
#pragma unroll
    for (int c = 0; c < 17; c++) {
        const float* plane = g_h1p + (size_t)c * NPIX + (size_t)b * HW;
        const float* wr = &swt[c * 9];
#pragma unroll
        for (int dy = -1; dy <= 1; dy++) {
            int yy = y + dy;
            if ((unsigned)yy > 255u) continue;
#pragma unroll
            for (int dx = -1; dx <= 1; dx++) {
                int xxp = x + dx;
                if ((unsigned)xxp > 255u) continue;
                acc += plane[yy * 256 + xxp] * wr[(dy + 1) * 3 + (dx + 1)];
            }
        }
    }
    g_sa[g] = 1.0f / (1.0f + __expf(-acc));
}

// ======================= K4: window score, warp-per-window =======================
__global__ __launch_bounds__(256) void k_score(
    const float* __restrict__ m1W, const float* __restrict__ m1b,
    const float* __restrict__ m2W, const float* __restrict__ m2b)
{
    int t = threadIdx.x, lane = t & 31, warp = t >> 5;
    int gw = blockIdx.x * 8 + warp;            // 0..2047
    int b = gw >> 10, w = gw & (NW - 1);
    int wy = w >> 5, wx = w & 31;
    int qy = lane >> 2, qx2 = (lane & 3) * 2;
    int tok = qy * 8 + qx2;

    u64 xv = *(const u64*)(g_xm + b * HW + (wy * 8 + qy) * 256 + wx * 8 + qx2);
    u64 pj[4];
#pragma unroll
    for (int j2 = 0; j2 < 4; j2++) {
        u64 w0 = *(const u64*)(m1W + (2*j2) * 64 + tok);
        u64 w1 = *(const u64*)(m1W + (2*j2+1) * 64 + tok);
        pj[j2] = pack2(hadd2(mul2(xv, w0)), hadd2(mul2(xv, w1)));
    }
#pragma unroll
    for (int s = 16; s > 0; s >>= 1) {
#pragma unroll
        for (int j2 = 0; j2 < 4; j2++)
            pj[j2] = add2(pj[j2], __shfl_xor_sync(0xffffffffu, pj[j2], s));
    }
    if (lane == 0) {
        float z[8];
#pragma unroll
        for (int j2 = 0; j2 < 4; j2++) { z[2*j2] = lo2(pj[j2]); z[2*j2+1] = hi2(pj[j2]); }
        float l0 = m2b[0], l1 = m2b[1];
#pragma unroll
        for (int j = 0; j < 8; j++) {
            float a = z[j] + m1b[j];
            a = (a >= 0.f) ? a : 0.1f * a;
            l0 += a * m2W[j]; l1 += a * m2W[8 + j];
        }
        g_score[gw] = 1.0f / (1.0f + __expf(l1 - l0));
    }
}

// ======================= K5: deterministic rank -> top-512 =======================
__global__ __launch_bounds__(1024) void k_rank()
{
    __shared__ float s[NW];
    int b = blockIdx.x;
    int i = threadIdx.x;
    s[i] = g_score[b * NW + i];
    __syncthreads();
    float si = s[i];
    int r = 0;
    for (int j = 0; j < NW; j++) {
        float sj = s[j];
        r += (sj > si) || (sj == si && j < i);
    }
    if (r < KEEP) {
        g_hard[b * KEEP + r] = i;
        g_ishard[b * NW + i] = 1;
    } else {
        g_ishard[b * NW + i] = 0;
    }
}

// ======================= K6: attention (unchanged core) =======================
#define ATTN_SMEM (144*64*4*2 + 64*68*4 + 184*8*2)
__global__ __launch_bounds__(256) void k_attn(
    const float* __restrict__ relh, const float* __restrict__ relw)
{
    extern __shared__ __align__(16) char dyn[];
    float* ks = (float*)dyn;
    float* vs = ks + 144*64;
    float* qs = vs + 144*64;
    u64* srw  = (u64*)(qs + 64*68);
    u64* srh  = srw + 184;

    int t = threadIdx.x;
    int head = t >> 6, tok = t & 63;
    int b = blockIdx.x >> 9;
    int w = g_hard[blockIdx.x];
    int wy = w >> 5, wx = w & 31;

    u64 s2 = pack2(0.25f, 0.25f);
    const u64* rw64 = (const u64*)relw;
    const u64* rh64 = (const u64*)relh;
    for (int i = t; i < 184; i += 256) {
        srw[i] = mul2(rw64[i], s2);
        srh[i] = mul2(rh64[i], s2);
    }

    int y0 = wy * 8 - 2, x0 = wx * 8 - 2;
#pragma unroll
    for (int i = 0; i < 9; i++) {
        int fidx = i * 256 + t;
        int kk = fidx >> 4, c4 = fidx & 15;
        int yy = y0 + kk / 12, xxp = x0 + kk % 12;
        float4 kv = make_float4(0.f, 0.f, 0.f, 0.f), vv = kv;
        if ((unsigned)yy < 256u && (unsigned)xxp < 256u) {
            size_t base = ((size_t)(b * HW + yy * 256 + xxp)) * 64 + 4 * c4;
            kv = *(const float4*)(g_k + base);
            vv = *(const float4*)(g_v + base);
            kv.x *= 0.25f; kv.y *= 0.25f; kv.z *= 0.25f; kv.w *= 0.25f;
        }
        *(float4*)(ks + kk * 64 + 4 * c4) = kv;
        *(float4*)(vs + kk * 64 + 4 * c4) = vv;
    }
#pragma unroll
    for (int i = 0; i < 4; i++) {
        int fidx = i * 256 + t;
        int tk = fidx >> 4, c4 = fidx & 15;
        int py = wy * 8 + (tk >> 3), px = wx * 8 + (tk & 7);
        float4 qv = *(const float4*)(g_q + ((size_t)(b * HW + py * 256 + px)) * 64 + 4 * c4);
        *(float4*)(qs + tk * 68 + 4 * c4) = qv;
    }
    __syncthreads();

    u64 q2[8];
    const u64* qrow = (const u64*)(qs + tok * 68 + head * 16);
#pragma unroll
    for (int i = 0; i < 8; i++) q2[i] = qrow[i];

    int qy = tok >> 3, qx = tok & 7;

    float rwv[12], rhv[12];
#pragma unroll
    for (int k2 = 0; k2 < 12; k2++) {
        const u64* pw = &srw[(k2 - qx + 11) * 8];
        const u64* ph = &srh[(k2 - qy + 11) * 8];
        u64 a0 = 0, a1 = 0, c0 = 0, c1 = 0;
#pragma unroll
        for (int i = 0; i < 8; i += 2) {
            a0 = fma2(q2[i],   pw[i],   a0);
            a1 = fma2(q2[i+1], pw[i+1], a1);
            c0 = fma2(q2[i],   ph[i],   c0);
            c1 = fma2(q2[i+1], ph[i+1], c1);
        }
        rwv[k2] = hadd2(a0) + hadd2(a1);
        rhv[k2] = hadd2(c0) + hadd2(c1);
    }

    float m = -1e30f;
    for (int ky = 0; ky < 12; ky++) {
        float rh2 = rhv[ky];
#pragma unroll
        for (int kx = 0; kx < 12; kx++) {
            const u64* kr = (const u64*)(ks + (ky * 12 + kx) * 64 + head * 16);
            u64 a0 = 0, a1 = 0;
#pragma unroll
            for (int i = 0; i < 8; i += 2) {
                a0 = fma2(q2[i],   kr[i],   a0);
                a1 = fma2(q2[i+1], kr[i+1], a1);
            }
            float l = hadd2(a0) + hadd2(a1) + rwv[kx] + rh2;
            m = fmaxf(m, l);
        }
    }

    float sum = 0.f;
    u64 acc[8] = {0,0,0,0,0,0,0,0};
    for (int ky = 0; ky < 12; ky++) {
        float rh2 = rhv[ky];
#pragma unroll
        for (int kx = 0; kx < 12; kx++) {
            int kk = ky * 12 + kx;
            const u64* kr = (const u64*)(ks + kk * 64 + head * 16);
            u64 a0 = 0, a1 = 0;
#pragma unroll
            for (int i = 0; i < 8; i += 2) {
                a0 = fma2(q2[i],   kr[i],   a0);
                a1 = fma2(q2[i+1], kr[i+1], a1);
            }
            float l = hadd2(a0) + hadd2(a1) + rwv[kx] + rh2;
            float wg = __expf(l - m);
            sum += wg;
            u64 w2 = pack2(wg, wg);
            const u64* vr = (const u64*)(vs + kk * 64 + head * 16);
#pragma unroll
            for (int i = 0; i < 8; i++) acc[i] = fma2(w2, vr[i], acc[i]);
        }
    }
    float invs = 1.0f / sum;
    u64 inv2 = pack2(invs, invs);
    u64* oq = (u64*)(qs + tok * 68 + head * 16);
#pragma unroll
    for (int i = 0; i < 8; i++) oq[i] = mul2(acc[i], inv2);
    __syncthreads();

#pragma unroll
    for (int i = 0; i < 4; i++) {
        int fidx = i * 256 + t;
        int tk = fidx >> 4, c4 = fidx & 15;
        int py = wy * 8 + (tk >> 3), px = wx * 8 + (tk & 7);
        float4 ov = *(const float4*)(qs + tk * 68 + 4 * c4);
        *(float4*)(g_mix + ((size_t)(b * HW + py * 256 + px)) * 64 + 4 * c4) = ov;
    }
}

// ======================= K7: final conv via tf32 mma (3x split) =======================
// block 256, tile M=128px, N=64oc, K=64ic.
// smem: sAh/sAl [px][68]ic, sBh/sBl [oc][68]ic
#define FINAL_SMEM ((128*68*2 + 64*68*2) * 4)
__global__ __launch_bounds__(256) void k_final(
    const float* __restrict__ Wout, const float* __restrict__ bout,
    float* __restrict__ out)
{
    extern __shared__ __align__(16) u32 sm[];
    u32* sAh = sm;                 // [128][68]
    u32* sAl = sAh + 128*68;
    u32* sBh = sAl + 128*68;       // [64][68]
    u32* sBl = sBh + 64*68;

    int t = threadIdx.x;
    int p0 = blockIdx.x * 128;
    int bb = p0 >> 16, ploc = p0 & (HW - 1);

    // stage selected input (hard: mix, easy: v*sa) -> tf32 hi/lo [px][ic]
#pragma unroll
    for (int i = 0; i < 8; i++) {
        int fidx = i * 256 + t;
        int px = fidx >> 4, c4 = (fidx & 15) << 2;
        int g = p0 + px;
        int p = g & (HW - 1);
        int wdw = ((p >> 11) << 5) | ((p >> 3) & 31);
        float4 v;
        if (g_ishard[(g >> 16) * NW + wdw]) {
            v = *(const float4*)(g_mix + (size_t)g * 64 + c4);
        } else {
            v = *(const float4*)(g_v + (size_t)g * 64 + c4);
            float s = g_sa[g];
            v.x *= s; v.y *= s; v.z *= s; v.w *= s;
        }
        uint4 h, l;
        tf32split(v.x, h.x, l.x); tf32split(v.y, h.y, l.y);
        tf32split(v.z, h.z, l.z); tf32split(v.w, h.w, l.w);
        *(uint4*)(sAh + px * 68 + c4) = h;
        *(uint4*)(sAl + px * 68 + c4) = l;
    }
    // stage Wout [oc][ic]
#pragma unroll
    for (int i = 0; i < 4; i++) {
        int widx = i * 256 + t;
        int oc = widx >> 4, ic4 = (widx & 15) << 2;
        float4 v = *(const float4*)(Wout + oc * 64 + ic4);
        uint4 h, l;
        tf32split(v.x, h.x, l.x); tf32split(v.y, h.y, l.y);
        tf32split(v.z, h.z, l.z); tf32split(v.w, h.w, l.w);
        *(uint4*)(sBh + oc * 68 + ic4) = h;
        *(uint4*)(sBl + oc * 68 + ic4) = l;
    }
    __syncthreads();

    int lane = t & 31, warp = t >> 5;
    int g = lane >> 2, i4 = lane & 3;
    int mg = warp >> 1, ng = warp & 1;   // 4 m-groups x 2 n-groups; warp: 2 m-tiles x 4 n-tiles

    float acc[2][4][4];
#pragma unroll
    for (int mt = 0; mt < 2; mt++)
#pragma unroll
        for (int nt = 0; nt < 4; nt++)
#pragma unroll
            for (int c = 0; c < 4; c++) acc[mt][nt][c] = 0.f;

#pragma unroll
    for (int kt = 0; kt < 8; kt++) {
        u32 ah[2][4], al[2][4];
#pragma unroll
        for (int mt = 0; mt < 2; mt++) {
            int mrow = mg * 32 + mt * 16 + g;
            const u32* pA = sAh + mrow * 68 + kt * 8 + i4;
            const u32* qA = sAl + mrow * 68 + kt * 8 + i4;
            ah[mt][0] = pA[0]; ah[mt][1] = pA[8*68]; ah[mt][2] = pA[4]; ah[mt][3] = pA[8*68+4];
            al[mt][0] = qA[0]; al[mt][1] = qA[8*68]; al[mt][2] = qA[4]; al[mt][3] = qA[8*68+4];
        }
        u32 bh[4][2], bl[4][2];
#pragma unroll
        for (int nt = 0; nt < 4; nt++) {
            int ocol = ng * 32 + nt * 8 + g;
            const u32* pB = sBh + ocol * 68 + kt * 8 + i4;
            const u32* qB = sBl + ocol * 68 + kt * 8 + i4;
            bh[nt][0] = pB[0]; bh[nt][1] = pB[4];
            bl[nt][0] = qB[0]; bl[nt][1] = qB[4];
        }
#pragma unroll
        for (int mt = 0; mt < 2; mt++)
#pragma unroll
            for (int nt = 0; nt < 4; nt++) {
                mma8(acc[mt][nt], ah[mt], bh[nt]);
                mma8(acc[mt][nt], ah[mt], bl[nt]);
                mma8(acc[mt][nt], al[mt], bh[nt]);
            }
    }

    // epilogue: NCHW scalar stores (8px-contiguous runs per reg)
    float* obase = out + (size_t)bb * 64 * HW + ploc;
#pragma unroll
    for (int nt = 0; nt < 4; nt++) {
        int oc0 = ng * 32 + nt * 8 + 2 * i4;
        float b0 = bout[oc0], b1 = bout[oc0 + 1];
#pragma unroll
        for (int mt = 0; mt < 2; mt++) {
            int pxr = mg * 32 + mt * 16 + g;
            float* po = obase + (size_t)oc0 * HW + pxr;
            po[0]      = acc[mt][nt][0] + b0;
            po[HW]     = acc[mt][nt][1] + b1;
            po[8]      = acc[mt][nt][2] + b0;
            po[HW + 8] = acc[mt][nt][3] + b1;
        }
    }
}

// ======================= launch =======================
extern "C" void kernel_launch(void* const* d_in, const int* in_sizes, int n_in,
                              void* d_out, int out_size)
{
    const float* x    = (const float*)d_in[0];
    const float* cg   = (const float*)d_in[1];
    const float* Wq   = (const float*)d_in[2];
    const float* bq   = (const float*)d_in[3];
    const float* Wk   = (const float*)d_in[4];
    const float* bk   = (const float*)d_in[5];
    const float* Wv   = (const float*)d_in[6];
    const float* bv   = (const float*)d_in[7];
    const float* Wout = (const float*)d_in[8];
    const float* bout = (const float*)d_in[9];
    const float* relh = (const float*)d_in[10];
    const float* relw = (const float*)d_in[11];
    const float* pinW = (const float*)d_in[12];
    const float* pinb = (const float*)d_in[13];
    const float* lnw  = (const float*)d_in[14];
    const float* lnb  = (const float*)d_in[15];
    const float* saW  = (const float*)d_in[16];
    const float* sab  = (const float*)d_in[17];
    const float* m1W  = (const float*)d_in[18];
    const float* m1b  = (const float*)d_in[19];
    const float* m2W  = (const float*)d_in[20];
    const float* m2b  = (const float*)d_in[21];
    float* out = (float*)d_out;

    cudaFuncSetAttribute(k_qkv,   cudaFuncAttributeMaxDynamicSharedMemorySize, QKV_SMEM);
    cudaFuncSetAttribute(k_attn,  cudaFuncAttributeMaxDynamicSharedMemorySize, ATTN_SMEM);
    cudaFuncSetAttribute(k_final, cudaFuncAttributeMaxDynamicSharedMemorySize, FINAL_SMEM);

    k_qkv  <<<NPIX / 128, 256, QKV_SMEM>>>(x, Wq, bq, Wk, bk, Wv, bv);
    k_pin  <<<NPIX / 128, 128>>>(cg, pinW, pinb, lnw, lnb);
    k_sa   <<<NPIX / 256, 256>>>(saW, sab);
    k_score<<<256, 256>>>(m1W, m1b, m2W, m2b);
    k_rank <<<BATCH, 1024>>>();
    k_attn <<<BATCH * KEEP, 256, ATTN_SMEM>>>(relh, relw);
    k_final<<<NPIX / 128, 256, FINAL_SMEM>>>(Wout, bout, out);
}